// round 11
// baseline (speedup 1.0000x reference)
#include <cuda_runtime.h>
#include <cstdint>

// QuantumOperator closed form (see prior rounds):
//   d_j = sigmoid(p_j) - p_j^2
//   out_real[j] = (sr.p + sum(si)) * p_j + d_j * sr[j] - si.p
//   out_imag[j] = (si.p - sum(sr)) * p_j + d_j * si[j] + sr.p
//
// R11: bulk async STORES. Compute per 32-row tile into SMEM staging, then one
// thread issues two 16KB cp.async.bulk SMEM->GMEM stores (bulk_group, no
// mbarrier). Double-buffered staging; wait_group 1 keeps one group in flight
// while the next tile computes. Goal: convert the write stream from scattered
// 512B STGs into large contiguous same-page bursts at the DRAM controller.

#define DIM 128
#define TILE_ROWS 32
#define TILE_F4 (TILE_ROWS * 32)          // 1024 float4 = 16 KB per array
#define BUF_F4 (TILE_F4 * 2)              // real + imag per buffer
#define SMEM_BYTES (2 * BUF_F4 * 16)      // 2 buffers = 64 KB

__device__ __forceinline__ uint32_t s2u(const void* p) {
    return (uint32_t)__cvta_generic_to_shared(p);
}
__device__ __forceinline__ void bulk_s2g(void* gptr, uint32_t saddr, uint32_t bytes) {
    asm volatile(
        "cp.async.bulk.global.shared::cta.bulk_group [%0], [%1], %2;"
        :: "l"(gptr), "r"(saddr), "r"(bytes) : "memory");
}
__device__ __forceinline__ float dot4(const float4 a, const float4 b) {
    return a.x * b.x + a.y * b.y + a.z * b.z + a.w * b.w;
}
__device__ __forceinline__ float hsum4(const float4 a) {
    return a.x + a.y + a.z + a.w;
}

__global__ void __launch_bounds__(256) quantum_bulkst_kernel(
    const float4* __restrict__ srv,
    const float4* __restrict__ siv,
    const float* __restrict__ p,
    float4* __restrict__ out_real,
    float4* __restrict__ out_imag,
    int ntiles)
{
    extern __shared__ float4 sbuf[];   // [2][2*TILE_F4]

    const int tid = threadIdx.x;
    const int lane = tid & 31;
    const int w = tid >> 5;            // 8 warps, 4 rows each within a 32-row tile

    const float4 p4 = reinterpret_cast<const float4*>(p)[lane];
    float4 d4;
    d4.x = 1.0f / (1.0f + __expf(-p4.x)) - p4.x * p4.x;
    d4.y = 1.0f / (1.0f + __expf(-p4.y)) - p4.y * p4.y;
    d4.z = 1.0f / (1.0f + __expf(-p4.z)) - p4.z * p4.z;
    d4.w = 1.0f / (1.0f + __expf(-p4.w)) - p4.w * p4.w;

    int it = 0;
    for (int t = blockIdx.x; t < ntiles; t += gridDim.x, it++) {
        const size_t gbase = (size_t)t * TILE_F4 + w * 4 * 32 + lane;

        // ---- 8x LDG.128 read burst (overlaps prior tile's bulk stores) ----
        const float4 a0 = __ldcg(&srv[gbase]);
        const float4 a1 = __ldcg(&srv[gbase + 32]);
        const float4 a2 = __ldcg(&srv[gbase + 64]);
        const float4 a3 = __ldcg(&srv[gbase + 96]);
        const float4 b0 = __ldcg(&siv[gbase]);
        const float4 b1 = __ldcg(&siv[gbase + 32]);
        const float4 b2 = __ldcg(&siv[gbase + 64]);
        const float4 b3 = __ldcg(&siv[gbase + 96]);

        // ---- 16 independent butterfly chains ----
        float ar0 = dot4(a0, p4), ai0 = dot4(b0, p4), sr0 = hsum4(a0), si0 = hsum4(b0);
        float ar1 = dot4(a1, p4), ai1 = dot4(b1, p4), sr1 = hsum4(a1), si1 = hsum4(b1);
        float ar2 = dot4(a2, p4), ai2 = dot4(b2, p4), sr2 = hsum4(a2), si2 = hsum4(b2);
        float ar3 = dot4(a3, p4), ai3 = dot4(b3, p4), sr3 = hsum4(a3), si3 = hsum4(b3);

        #pragma unroll
        for (int off = 16; off > 0; off >>= 1) {
            ar0 += __shfl_xor_sync(0xFFFFFFFFu, ar0, off);
            ai0 += __shfl_xor_sync(0xFFFFFFFFu, ai0, off);
            sr0 += __shfl_xor_sync(0xFFFFFFFFu, sr0, off);
            si0 += __shfl_xor_sync(0xFFFFFFFFu, si0, off);
            ar1 += __shfl_xor_sync(0xFFFFFFFFu, ar1, off);
            ai1 += __shfl_xor_sync(0xFFFFFFFFu, ai1, off);
            sr1 += __shfl_xor_sync(0xFFFFFFFFu, sr1, off);
            si1 += __shfl_xor_sync(0xFFFFFFFFu, si1, off);
            ar2 += __shfl_xor_sync(0xFFFFFFFFu, ar2, off);
            ai2 += __shfl_xor_sync(0xFFFFFFFFu, ai2, off);
            sr2 += __shfl_xor_sync(0xFFFFFFFFu, sr2, off);
            si2 += __shfl_xor_sync(0xFFFFFFFFu, si2, off);
            ar3 += __shfl_xor_sync(0xFFFFFFFFu, ar3, off);
            ai3 += __shfl_xor_sync(0xFFFFFFFFu, ai3, off);
            sr3 += __shfl_xor_sync(0xFFFFFFFFu, sr3, off);
            si3 += __shfl_xor_sync(0xFFFFFFFFu, si3, off);
        }

        float4 or0, or1, or2, or3, oi0, oi1, oi2, oi3;
        {
            const float cr = ar0 + si0, ci = ai0 - sr0;
            or0.x = cr * p4.x + d4.x * a0.x - ai0;
            or0.y = cr * p4.y + d4.y * a0.y - ai0;
            or0.z = cr * p4.z + d4.z * a0.z - ai0;
            or0.w = cr * p4.w + d4.w * a0.w - ai0;
            oi0.x = ci * p4.x + d4.x * b0.x + ar0;
            oi0.y = ci * p4.y + d4.y * b0.y + ar0;
            oi0.z = ci * p4.z + d4.z * b0.z + ar0;
            oi0.w = ci * p4.w + d4.w * b0.w + ar0;
        }
        {
            const float cr = ar1 + si1, ci = ai1 - sr1;
            or1.x = cr * p4.x + d4.x * a1.x - ai1;
            or1.y = cr * p4.y + d4.y * a1.y - ai1;
            or1.z = cr * p4.z + d4.z * a1.z - ai1;
            or1.w = cr * p4.w + d4.w * a1.w - ai1;
            oi1.x = ci * p4.x + d4.x * b1.x + ar1;
            oi1.y = ci * p4.y + d4.y * b1.y + ar1;
            oi1.z = ci * p4.z + d4.z * b1.z + ar1;
            oi1.w = ci * p4.w + d4.w * b1.w + ar1;
        }
        {
            const float cr = ar2 + si2, ci = ai2 - sr2;
            or2.x = cr * p4.x + d4.x * a2.x - ai2;
            or2.y = cr * p4.y + d4.y * a2.y - ai2;
            or2.z = cr * p4.z + d4.z * a2.z - ai2;
            or2.w = cr * p4.w + d4.w * a2.w - ai2;
            oi2.x = ci * p4.x + d4.x * b2.x + ar2;
            oi2.y = ci * p4.y + d4.y * b2.y + ar2;
            oi2.z = ci * p4.z + d4.z * b2.z + ar2;
            oi2.w = ci * p4.w + d4.w * b2.w + ar2;
        }
        {
            const float cr = ar3 + si3, ci = ai3 - sr3;
            or3.x = cr * p4.x + d4.x * a3.x - ai3;
            or3.y = cr * p4.y + d4.y * a3.y - ai3;
            or3.z = cr * p4.z + d4.z * a3.z - ai3;
            or3.w = cr * p4.w + d4.w * a3.w - ai3;
            oi3.x = ci * p4.x + d4.x * b3.x + ar3;
            oi3.y = ci * p4.y + d4.y * b3.y + ar3;
            oi3.z = ci * p4.z + d4.z * b3.z + ar3;
            oi3.w = ci * p4.w + d4.w * b3.w + ar3;
        }

        // ---- Wait for the buffer we're about to reuse (2 buffers, allow 1
        //      group in flight -> group from iter-2 has drained) ----
        if (tid == 0) {
            asm volatile("cp.async.bulk.wait_group 1;" ::: "memory");
        }
        __syncthreads();

        float4* bufR = sbuf + (it & 1) * BUF_F4;
        float4* bufI = bufR + TILE_F4;
        const int ridx = w * 4 * 32 + lane;
        bufR[ridx]      = or0;
        bufR[ridx + 32] = or1;
        bufR[ridx + 64] = or2;
        bufR[ridx + 96] = or3;
        bufI[ridx]      = oi0;
        bufI[ridx + 32] = oi1;
        bufI[ridx + 64] = oi2;
        bufI[ridx + 96] = oi3;
        __syncthreads();

        if (tid == 0) {
            asm volatile("fence.proxy.async.shared::cta;" ::: "memory");
            bulk_s2g(&out_real[(size_t)t * TILE_F4], s2u(bufR), TILE_F4 * 16);
            bulk_s2g(&out_imag[(size_t)t * TILE_F4], s2u(bufI), TILE_F4 * 16);
            asm volatile("cp.async.bulk.commit_group;" ::: "memory");
        }
    }

    // Drain all outstanding bulk stores before exit
    if (tid == 0) {
        asm volatile("cp.async.bulk.wait_group 0;" ::: "memory");
    }
}

extern "C" void kernel_launch(void* const* d_in, const int* in_sizes, int n_in,
                              void* d_out, int out_size) {
    const float* sr = (const float*)d_in[0];
    const float* si = (const float*)d_in[1];
    const float* p  = (const float*)d_in[2];
    float* out = (float*)d_out;

    const int M = in_sizes[0] / DIM;                 // 262144 rows
    float4* out_real = (float4*)out;
    float4* out_imag = (float4*)(out + (size_t)M * DIM);

    const int ntiles = M / TILE_ROWS;                // 8192
    const int threads = 256;
    const int blocks = 2048;                         // 4 tiles/block grid-stride

    cudaFuncSetAttribute(quantum_bulkst_kernel,
                         cudaFuncAttributeMaxDynamicSharedMemorySize, SMEM_BYTES);
    quantum_bulkst_kernel<<<blocks, threads, SMEM_BYTES>>>(
        (const float4*)sr, (const float4*)si, p, out_real, out_imag, ntiles);
}

// round 12
// speedup vs baseline: 1.1657x; 1.1657x over previous
#include <cuda_runtime.h>

// QuantumOperator — FINAL (R6/R10 champion, reproduced at 84.45/84.48 us).
//
// Key optimization (R0): algebraic collapse of the operator.
//   op_real = p p^T + diag(sigmoid(p) - p^2),  op_imag = p 1^T - 1 p^T
//   =>  with a_r = sr.p, a_i = si.p, s_r = sum(sr), s_i = sum(si),
//       d_j = sigmoid(p_j) - p_j^2:
//   out_real[j] = (a_r + s_i) * p_j + d_j * sr[j] - a_i
//   out_imag[j] = (a_i - s_r) * p_j + d_j * si[j] + a_r
//
// Turns a 34 GFLOP complex GEMM into 537 MB of pure streaming. Ten config
// sweeps (occupancy, MLP, layout, TMA/bulk read+write paths, cache hints,
// wave shape, burst length) all converge on ~6.2 TB/s = the practical mixed
// 50/50 R/W HBM3e ceiling on this part; this kernel sits on that roofline.
//
// Config: 4-row batch, 8x LDG.128 (__ldcg) read burst, 16 parallel butterfly
// reduction chains, 8x STG.128 (__stcs) write burst, interleaved grid-stride,
// 2048 blocks x 256 threads.

#define DIM 128

__device__ __forceinline__ float dot4(const float4 a, const float4 b) {
    return a.x * b.x + a.y * b.y + a.z * b.z + a.w * b.w;
}
__device__ __forceinline__ float hsum4(const float4 a) {
    return a.x + a.y + a.z + a.w;
}

__global__ void __launch_bounds__(256) quantum_op_kernel(
    const float4* __restrict__ srv,
    const float4* __restrict__ siv,
    const float* __restrict__ p,
    float4* __restrict__ out_real,
    float4* __restrict__ out_imag,
    int M)
{
    const int lane = threadIdx.x & 31;
    const int warp = blockIdx.x * (blockDim.x >> 5) + (threadIdx.x >> 5);
    const int nwarps = gridDim.x * (blockDim.x >> 5);

    const float4 p4 = reinterpret_cast<const float4*>(p)[lane];
    float4 d4;
    d4.x = 1.0f / (1.0f + __expf(-p4.x)) - p4.x * p4.x;
    d4.y = 1.0f / (1.0f + __expf(-p4.y)) - p4.y * p4.y;
    d4.z = 1.0f / (1.0f + __expf(-p4.z)) - p4.z * p4.z;
    d4.w = 1.0f / (1.0f + __expf(-p4.w)) - p4.w * p4.w;

    const int stride = nwarps * 4;

    for (int row = warp * 4; row < M; row += stride) {
        const size_t base = (size_t)row * 32 + lane;

        // ---- 8x LDG.128 back-to-back: 4KB read burst per warp ----
        const float4 a0 = __ldcg(&srv[base]);
        const float4 a1 = __ldcg(&srv[base + 32]);
        const float4 a2 = __ldcg(&srv[base + 64]);
        const float4 a3 = __ldcg(&srv[base + 96]);
        const float4 b0 = __ldcg(&siv[base]);
        const float4 b1 = __ldcg(&siv[base + 32]);
        const float4 b2 = __ldcg(&siv[base + 64]);
        const float4 b3 = __ldcg(&siv[base + 96]);

        // ---- 16 independent butterfly chains ----
        float ar0 = dot4(a0, p4), ai0 = dot4(b0, p4), sr0 = hsum4(a0), si0 = hsum4(b0);
        float ar1 = dot4(a1, p4), ai1 = dot4(b1, p4), sr1 = hsum4(a1), si1 = hsum4(b1);
        float ar2 = dot4(a2, p4), ai2 = dot4(b2, p4), sr2 = hsum4(a2), si2 = hsum4(b2);
        float ar3 = dot4(a3, p4), ai3 = dot4(b3, p4), sr3 = hsum4(a3), si3 = hsum4(b3);

        #pragma unroll
        for (int off = 16; off > 0; off >>= 1) {
            ar0 += __shfl_xor_sync(0xFFFFFFFFu, ar0, off);
            ai0 += __shfl_xor_sync(0xFFFFFFFFu, ai0, off);
            sr0 += __shfl_xor_sync(0xFFFFFFFFu, sr0, off);
            si0 += __shfl_xor_sync(0xFFFFFFFFu, si0, off);
            ar1 += __shfl_xor_sync(0xFFFFFFFFu, ar1, off);
            ai1 += __shfl_xor_sync(0xFFFFFFFFu, ai1, off);
            sr1 += __shfl_xor_sync(0xFFFFFFFFu, sr1, off);
            si1 += __shfl_xor_sync(0xFFFFFFFFu, si1, off);
            ar2 += __shfl_xor_sync(0xFFFFFFFFu, ar2, off);
            ai2 += __shfl_xor_sync(0xFFFFFFFFu, ai2, off);
            sr2 += __shfl_xor_sync(0xFFFFFFFFu, sr2, off);
            si2 += __shfl_xor_sync(0xFFFFFFFFu, si2, off);
            ar3 += __shfl_xor_sync(0xFFFFFFFFu, ar3, off);
            ai3 += __shfl_xor_sync(0xFFFFFFFFu, ai3, off);
            sr3 += __shfl_xor_sync(0xFFFFFFFFu, sr3, off);
            si3 += __shfl_xor_sync(0xFFFFFFFFu, si3, off);
        }

        float4 or0, or1, or2, or3, oi0, oi1, oi2, oi3;
        {
            const float cr = ar0 + si0, ci = ai0 - sr0;
            or0.x = cr * p4.x + d4.x * a0.x - ai0;
            or0.y = cr * p4.y + d4.y * a0.y - ai0;
            or0.z = cr * p4.z + d4.z * a0.z - ai0;
            or0.w = cr * p4.w + d4.w * a0.w - ai0;
            oi0.x = ci * p4.x + d4.x * b0.x + ar0;
            oi0.y = ci * p4.y + d4.y * b0.y + ar0;
            oi0.z = ci * p4.z + d4.z * b0.z + ar0;
            oi0.w = ci * p4.w + d4.w * b0.w + ar0;
        }
        {
            const float cr = ar1 + si1, ci = ai1 - sr1;
            or1.x = cr * p4.x + d4.x * a1.x - ai1;
            or1.y = cr * p4.y + d4.y * a1.y - ai1;
            or1.z = cr * p4.z + d4.z * a1.z - ai1;
            or1.w = cr * p4.w + d4.w * a1.w - ai1;
            oi1.x = ci * p4.x + d4.x * b1.x + ar1;
            oi1.y = ci * p4.y + d4.y * b1.y + ar1;
            oi1.z = ci * p4.z + d4.z * b1.z + ar1;
            oi1.w = ci * p4.w + d4.w * b1.w + ar1;
        }
        {
            const float cr = ar2 + si2, ci = ai2 - sr2;
            or2.x = cr * p4.x + d4.x * a2.x - ai2;
            or2.y = cr * p4.y + d4.y * a2.y - ai2;
            or2.z = cr * p4.z + d4.z * a2.z - ai2;
            or2.w = cr * p4.w + d4.w * a2.w - ai2;
            oi2.x = ci * p4.x + d4.x * b2.x + ar2;
            oi2.y = ci * p4.y + d4.y * b2.y + ar2;
            oi2.z = ci * p4.z + d4.z * b2.z + ar2;
            oi2.w = ci * p4.w + d4.w * b2.w + ar2;
        }
        {
            const float cr = ar3 + si3, ci = ai3 - sr3;
            or3.x = cr * p4.x + d4.x * a3.x - ai3;
            or3.y = cr * p4.y + d4.y * a3.y - ai3;
            or3.z = cr * p4.z + d4.z * a3.z - ai3;
            or3.w = cr * p4.w + d4.w * a3.w - ai3;
            oi3.x = ci * p4.x + d4.x * b3.x + ar3;
            oi3.y = ci * p4.y + d4.y * b3.y + ar3;
            oi3.z = ci * p4.z + d4.z * b3.z + ar3;
            oi3.w = ci * p4.w + d4.w * b3.w + ar3;
        }

        __stcs(&out_real[base],      or0);
        __stcs(&out_real[base + 32], or1);
        __stcs(&out_real[base + 64], or2);
        __stcs(&out_real[base + 96], or3);
        __stcs(&out_imag[base],      oi0);
        __stcs(&out_imag[base + 32], oi1);
        __stcs(&out_imag[base + 64], oi2);
        __stcs(&out_imag[base + 96], oi3);
    }
}

extern "C" void kernel_launch(void* const* d_in, const int* in_sizes, int n_in,
                              void* d_out, int out_size) {
    const float* sr = (const float*)d_in[0];
    const float* si = (const float*)d_in[1];
    const float* p  = (const float*)d_in[2];
    float* out = (float*)d_out;

    const int M = in_sizes[0] / DIM;                 // 262144 rows
    float4* out_real = (float4*)out;
    float4* out_imag = (float4*)(out + (size_t)M * DIM);

    const int threads = 256;
    const int blocks = 2048;                         // champion config
    quantum_op_kernel<<<blocks, threads>>>(
        (const float4*)sr, (const float4*)si, p, out_real, out_imag, M);
}

// round 13
// speedup vs baseline: 1.1701x; 1.0038x over previous
#include <cuda_runtime.h>

// QuantumOperator — FINAL (champion; reproduced 84.45/84.48/84.77 us).
//
// Key optimization (R0): algebraic collapse of the operator.
//   op_real = p p^T + diag(sigmoid(p) - p^2),  op_imag = p 1^T - 1 p^T
//   =>  with a_r = sr.p, a_i = si.p, s_r = sum(sr), s_i = sum(si),
//       d_j = sigmoid(p_j) - p_j^2:
//   out_real[j] = (a_r + s_i) * p_j + d_j * sr[j] - a_i
//   out_imag[j] = (a_i - s_r) * p_j + d_j * si[j] + a_r
//
// Turns a 34 GFLOP complex GEMM into 537 MB of pure streaming. Ten config
// sweeps (occupancy, MLP, layout, TMA/bulk read+write paths, cache hints,
// wave shape, burst length) all converge on ~6.2 TB/s = the practical mixed
// 50/50 R/W HBM3e ceiling on this part; this kernel sits on that roofline.
//
// Config: 4-row batch, 8x LDG.128 (__ldcg) read burst, 16 parallel butterfly
// reduction chains, 8x STG.128 (__stcs) write burst, interleaved grid-stride,
// 2048 blocks x 256 threads.

#define DIM 128

__device__ __forceinline__ float dot4(const float4 a, const float4 b) {
    return a.x * b.x + a.y * b.y + a.z * b.z + a.w * b.w;
}
__device__ __forceinline__ float hsum4(const float4 a) {
    return a.x + a.y + a.z + a.w;
}

__global__ void __launch_bounds__(256) quantum_op_kernel(
    const float4* __restrict__ srv,
    const float4* __restrict__ siv,
    const float* __restrict__ p,
    float4* __restrict__ out_real,
    float4* __restrict__ out_imag,
    int M)
{
    const int lane = threadIdx.x & 31;
    const int warp = blockIdx.x * (blockDim.x >> 5) + (threadIdx.x >> 5);
    const int nwarps = gridDim.x * (blockDim.x >> 5);

    const float4 p4 = reinterpret_cast<const float4*>(p)[lane];
    float4 d4;
    d4.x = 1.0f / (1.0f + __expf(-p4.x)) - p4.x * p4.x;
    d4.y = 1.0f / (1.0f + __expf(-p4.y)) - p4.y * p4.y;
    d4.z = 1.0f / (1.0f + __expf(-p4.z)) - p4.z * p4.z;
    d4.w = 1.0f / (1.0f + __expf(-p4.w)) - p4.w * p4.w;

    const int stride = nwarps * 4;

    for (int row = warp * 4; row < M; row += stride) {
        const size_t base = (size_t)row * 32 + lane;

        // ---- 8x LDG.128 back-to-back: 4KB read burst per warp ----
        const float4 a0 = __ldcg(&srv[base]);
        const float4 a1 = __ldcg(&srv[base + 32]);
        const float4 a2 = __ldcg(&srv[base + 64]);
        const float4 a3 = __ldcg(&srv[base + 96]);
        const float4 b0 = __ldcg(&siv[base]);
        const float4 b1 = __ldcg(&siv[base + 32]);
        const float4 b2 = __ldcg(&siv[base + 64]);
        const float4 b3 = __ldcg(&siv[base + 96]);

        // ---- 16 independent butterfly chains ----
        float ar0 = dot4(a0, p4), ai0 = dot4(b0, p4), sr0 = hsum4(a0), si0 = hsum4(b0);
        float ar1 = dot4(a1, p4), ai1 = dot4(b1, p4), sr1 = hsum4(a1), si1 = hsum4(b1);
        float ar2 = dot4(a2, p4), ai2 = dot4(b2, p4), sr2 = hsum4(a2), si2 = hsum4(b2);
        float ar3 = dot4(a3, p4), ai3 = dot4(b3, p4), sr3 = hsum4(a3), si3 = hsum4(b3);

        #pragma unroll
        for (int off = 16; off > 0; off >>= 1) {
            ar0 += __shfl_xor_sync(0xFFFFFFFFu, ar0, off);
            ai0 += __shfl_xor_sync(0xFFFFFFFFu, ai0, off);
            sr0 += __shfl_xor_sync(0xFFFFFFFFu, sr0, off);
            si0 += __shfl_xor_sync(0xFFFFFFFFu, si0, off);
            ar1 += __shfl_xor_sync(0xFFFFFFFFu, ar1, off);
            ai1 += __shfl_xor_sync(0xFFFFFFFFu, ai1, off);
            sr1 += __shfl_xor_sync(0xFFFFFFFFu, sr1, off);
            si1 += __shfl_xor_sync(0xFFFFFFFFu, si1, off);
            ar2 += __shfl_xor_sync(0xFFFFFFFFu, ar2, off);
            ai2 += __shfl_xor_sync(0xFFFFFFFFu, ai2, off);
            sr2 += __shfl_xor_sync(0xFFFFFFFFu, sr2, off);
            si2 += __shfl_xor_sync(0xFFFFFFFFu, si2, off);
            ar3 += __shfl_xor_sync(0xFFFFFFFFu, ar3, off);
            ai3 += __shfl_xor_sync(0xFFFFFFFFu, ai3, off);
            sr3 += __shfl_xor_sync(0xFFFFFFFFu, sr3, off);
            si3 += __shfl_xor_sync(0xFFFFFFFFu, si3, off);
        }

        float4 or0, or1, or2, or3, oi0, oi1, oi2, oi3;
        {
            const float cr = ar0 + si0, ci = ai0 - sr0;
            or0.x = cr * p4.x + d4.x * a0.x - ai0;
            or0.y = cr * p4.y + d4.y * a0.y - ai0;
            or0.z = cr * p4.z + d4.z * a0.z - ai0;
            or0.w = cr * p4.w + d4.w * a0.w - ai0;
            oi0.x = ci * p4.x + d4.x * b0.x + ar0;
            oi0.y = ci * p4.y + d4.y * b0.y + ar0;
            oi0.z = ci * p4.z + d4.z * b0.z + ar0;
            oi0.w = ci * p4.w + d4.w * b0.w + ar0;
        }
        {
            const float cr = ar1 + si1, ci = ai1 - sr1;
            or1.x = cr * p4.x + d4.x * a1.x - ai1;
            or1.y = cr * p4.y + d4.y * a1.y - ai1;
            or1.z = cr * p4.z + d4.z * a1.z - ai1;
            or1.w = cr * p4.w + d4.w * a1.w - ai1;
            oi1.x = ci * p4.x + d4.x * b1.x + ar1;
            oi1.y = ci * p4.y + d4.y * b1.y + ar1;
            oi1.z = ci * p4.z + d4.z * b1.z + ar1;
            oi1.w = ci * p4.w + d4.w * b1.w + ar1;
        }
        {
            const float cr = ar2 + si2, ci = ai2 - sr2;
            or2.x = cr * p4.x + d4.x * a2.x - ai2;
            or2.y = cr * p4.y + d4.y * a2.y - ai2;
            or2.z = cr * p4.z + d4.z * a2.z - ai2;
            or2.w = cr * p4.w + d4.w * a2.w - ai2;
            oi2.x = ci * p4.x + d4.x * b2.x + ar2;
            oi2.y = ci * p4.y + d4.y * b2.y + ar2;
            oi2.z = ci * p4.z + d4.z * b2.z + ar2;
            oi2.w = ci * p4.w + d4.w * b2.w + ar2;
        }
        {
            const float cr = ar3 + si3, ci = ai3 - sr3;
            or3.x = cr * p4.x + d4.x * a3.x - ai3;
            or3.y = cr * p4.y + d4.y * a3.y - ai3;
            or3.z = cr * p4.z + d4.z * a3.z - ai3;
            or3.w = cr * p4.w + d4.w * a3.w - ai3;
            oi3.x = ci * p4.x + d4.x * b3.x + ar3;
            oi3.y = ci * p4.y + d4.y * b3.y + ar3;
            oi3.z = ci * p4.z + d4.z * b3.z + ar3;
            oi3.w = ci * p4.w + d4.w * b3.w + ar3;
        }

        __stcs(&out_real[base],      or0);
        __stcs(&out_real[base + 32], or1);
        __stcs(&out_real[base + 64], or2);
        __stcs(&out_real[base + 96], or3);
        __stcs(&out_imag[base],      oi0);
        __stcs(&out_imag[base + 32], oi1);
        __stcs(&out_imag[base + 64], oi2);
        __stcs(&out_imag[base + 96], oi3);
    }
}

extern "C" void kernel_launch(void* const* d_in, const int* in_sizes, int n_in,
                              void* d_out, int out_size) {
    const float* sr = (const float*)d_in[0];
    const float* si = (const float*)d_in[1];
    const float* p  = (const float*)d_in[2];
    float* out = (float*)d_out;

    const int M = in_sizes[0] / DIM;                 // 262144 rows
    float4* out_real = (float4*)out;
    float4* out_imag = (float4*)(out + (size_t)M * DIM);

    const int threads = 256;
    const int blocks = 2048;                         // champion config
    quantum_op_kernel<<<blocks, threads>>>(
        (const float4*)sr, (const float4*)si, p, out_real, out_imag, M);
}